// round 5
// baseline (speedup 1.0000x reference)
#include <cuda_runtime.h>
#include <math.h>
#include <stdint.h>

// ---------------------------------------------------------------------------
// graphNet: 4-layer GCN (21->168->84->42->21) + log_softmax.
// Round-5: FFMA2 (fma.rn.f32x2) packed-fp32 GEMM (2x issue throughput),
// fused single-pass CSR build (atomic block-base scan), padded CSR gathers.
// Fix vs R4: bias read in GEMM epilogue is bounds-guarded (was OOB on b1).
// ---------------------------------------------------------------------------

#define N_MAX 100000
#define E_MAX 1600000
#define F_MAX 168
#define CSR_MAX (E_MAX + 4 * N_MAX)
#define SCAN_B 1024

struct __align__(8) Edge { int src; float w; };

__device__ float g_bufA[(size_t)N_MAX * F_MAX];
__device__ float g_bufB[(size_t)N_MAX * F_MAX];
__device__ int   g_ideg[N_MAX];
__device__ float g_dinv[N_MAX];
__device__ int   g_rowbeg[N_MAX];
__device__ int   g_cur[N_MAX];
__device__ int   g_counter[1];
__device__ Edge  g_csr[CSR_MAX];

// ---------------- packed fp32 helpers ----------------

__device__ __forceinline__ void ffma2(unsigned long long& acc,
                                      unsigned long long a, unsigned long long b) {
    asm("fma.rn.f32x2 %0, %1, %2, %0;" : "+l"(acc) : "l"(a), "l"(b));
}

__device__ __forceinline__ float2 unpack2(unsigned long long v) {
    float2 r;
    r.x = __uint_as_float((unsigned)(v & 0xffffffffull));
    r.y = __uint_as_float((unsigned)(v >> 32));
    return r;
}

// ---------------- init / degree ----------------

__global__ void k_init(int* __restrict__ ideg, int* __restrict__ cur,
                       int* __restrict__ counter, int n) {
    int i = blockIdx.x * blockDim.x + threadIdx.x;
    if (i < n) { ideg[i] = 0; cur[i] = 0; }
    if (i == 0) counter[0] = 0;
}

__global__ void k_count_deg(const int* __restrict__ ei, int* __restrict__ ideg, int E) {
    int e = blockIdx.x * blockDim.x + threadIdx.x;
    if (e < E) atomicAdd(&ideg[ei[E + e]], 1);
}

// ---------------- fused single-pass offsets ----------------
// Per block: scan padded degrees, grab a global base via atomicAdd (region
// order is arbitrary but each node gets a private, correctly sized region).
// Also computes dinv and zero-fills the pad slots of each row.

__global__ void k_offsets(const int* __restrict__ ideg, int* __restrict__ row_beg,
                          float* __restrict__ dinv, Edge* __restrict__ csr,
                          int* __restrict__ counter, int n) {
    __shared__ int s[SCAN_B];
    __shared__ int base_sh;
    int i = blockIdx.x * SCAN_B + threadIdx.x;
    int deg = (i < n) ? ideg[i] : 0;
    int pd = (deg + 3) & ~3;
    s[threadIdx.x] = pd;
    __syncthreads();
#pragma unroll
    for (int off = 1; off < SCAN_B; off <<= 1) {
        int t = (threadIdx.x >= off) ? s[threadIdx.x - off] : 0;
        __syncthreads();
        s[threadIdx.x] += t;
        __syncthreads();
    }
    if (threadIdx.x == SCAN_B - 1) base_sh = atomicAdd(counter, s[SCAN_B - 1]);
    __syncthreads();
    int base = base_sh;
    if (i < n) {
        int beg = base + s[threadIdx.x] - pd;
        row_beg[i] = beg;
        dinv[i] = rsqrtf((float)(deg + 1));
        Edge z; z.src = 0; z.w = 0.f;
        for (int p = deg; p < pd; p++) csr[beg + p] = z;
    }
}

// ---------------- CSR scatter ----------------

__global__ void k_scatter(const int* __restrict__ ei, const int* __restrict__ row_beg,
                          int* __restrict__ cur, const float* __restrict__ dinv,
                          Edge* __restrict__ csr, int E) {
    int e = blockIdx.x * blockDim.x + threadIdx.x;
    if (e < E) {
        int s = ei[e];
        int d = ei[E + e];
        int pos = atomicAdd(&cur[d], 1);
        float2 rec = make_float2(__int_as_float(s), dinv[s] * dinv[d]);
        *reinterpret_cast<float2*>(&csr[row_beg[d] + pos]) = rec;
    }
}

// ---------------- vector row load helper ----------------

template <int VW>
__device__ __forceinline__ void ldrow(float (&f)[VW], const float* __restrict__ p) {
    if (VW == 4) { float4 t = *(const float4*)p; f[0]=t.x; f[1]=t.y; f[2]=t.z; f[3]=t.w; }
    else if (VW == 2) { float2 t = *(const float2*)p; f[0]=t.x; f[1]=t.y; }
    else { f[0] = *p; }
}

// ---------------- fused CSR aggregation ----------------

template <int C, int VW, int SIN, int SOUT>
__global__ void k_agg(const float* __restrict__ h, const int* __restrict__ row_beg,
                      const int* __restrict__ ideg,
                      const Edge* __restrict__ csr, const float* __restrict__ dinv,
                      const float* __restrict__ bias, float* __restrict__ out, int n) {
    constexpr int L = C / VW;
    int v = (blockIdx.x * blockDim.x + threadIdx.x) >> 5;
    int lane = threadIdx.x & 31;
    if (v >= n) return;

    if (lane < L) {
        int beg = row_beg[v];
        int endp = beg + ((ideg[v] + 3) & ~3);
        const int off = lane * VW;
        float acc[VW];
#pragma unroll
        for (int k = 0; k < VW; k++) acc[k] = 0.f;

        int j = beg;
        for (; j + 8 <= endp; j += 8) {
            int4 e0 = *(const int4*)(csr + j);
            int4 e1 = *(const int4*)(csr + j + 2);
            int4 e2 = *(const int4*)(csr + j + 4);
            int4 e3 = *(const int4*)(csr + j + 6);
            float f[8][VW];
            ldrow<VW>(f[0], h + (size_t)e0.x * SIN + off);
            ldrow<VW>(f[1], h + (size_t)e0.z * SIN + off);
            ldrow<VW>(f[2], h + (size_t)e1.x * SIN + off);
            ldrow<VW>(f[3], h + (size_t)e1.z * SIN + off);
            ldrow<VW>(f[4], h + (size_t)e2.x * SIN + off);
            ldrow<VW>(f[5], h + (size_t)e2.z * SIN + off);
            ldrow<VW>(f[6], h + (size_t)e3.x * SIN + off);
            ldrow<VW>(f[7], h + (size_t)e3.z * SIN + off);
            float w[8];
            w[0] = __int_as_float(e0.y); w[1] = __int_as_float(e0.w);
            w[2] = __int_as_float(e1.y); w[3] = __int_as_float(e1.w);
            w[4] = __int_as_float(e2.y); w[5] = __int_as_float(e2.w);
            w[6] = __int_as_float(e3.y); w[7] = __int_as_float(e3.w);
#pragma unroll
            for (int i = 0; i < 8; i++)
#pragma unroll
                for (int k = 0; k < VW; k++) acc[k] = fmaf(w[i], f[i][k], acc[k]);
        }
        if (j < endp) {
            int4 e0 = *(const int4*)(csr + j);
            int4 e1 = *(const int4*)(csr + j + 2);
            float f[4][VW];
            ldrow<VW>(f[0], h + (size_t)e0.x * SIN + off);
            ldrow<VW>(f[1], h + (size_t)e0.z * SIN + off);
            ldrow<VW>(f[2], h + (size_t)e1.x * SIN + off);
            ldrow<VW>(f[3], h + (size_t)e1.z * SIN + off);
            float w[4];
            w[0] = __int_as_float(e0.y); w[1] = __int_as_float(e0.w);
            w[2] = __int_as_float(e1.y); w[3] = __int_as_float(e1.w);
#pragma unroll
            for (int i = 0; i < 4; i++)
#pragma unroll
                for (int k = 0; k < VW; k++) acc[k] = fmaf(w[i], f[i][k], acc[k]);
        }

        float dv = dinv[v];
        float s2 = dv * dv;
        float pvv[VW];
        ldrow<VW>(pvv, h + (size_t)v * SIN + off);
        float* po = out + (size_t)v * SOUT + off;
#pragma unroll
        for (int k = 0; k < VW; k++) {
            float r = fmaf(s2, pvv[k], acc[k]);
            if (bias) r = fmaxf(r + bias[off + k], 0.f);
            po[k] = r;
        }
    } else if (lane * VW < SOUT) {
        float* po = out + (size_t)v * SOUT + lane * VW;
#pragma unroll
        for (int k = 0; k < VW; k++) po[k] = 0.f;
    }
}

// ---------------- FFMA2 GEMM: C[N x M] = A[N x K] @ W[K x M] ----------------
// 256x32 block tile, 8x4 microtile, 256 threads, packed f32x2 FMA.
// B stored duplicated in smem so broadcast operands load pre-packed.

#define GBM 256
#define GBN 32
#define GBK 16

__global__ void __launch_bounds__(256)
k_gemm(const float* __restrict__ A, const float* __restrict__ W,
       const float* __restrict__ bias, float* __restrict__ Cout,
       int N, int K, int M, int SA, int SC, int fuse_bias_relu) {
    __shared__ float As[GBK][GBM];        // [k][row]
    __shared__ float Bs2[GBK][GBN * 2];   // [k][2*col] duplicated {b,b}

    int tid = threadIdx.x;
    int w = tid >> 5;
    int l = tid & 31;
    int bm = blockIdx.x * GBM;
    int bn = blockIdx.y * GBN;

    // row group: lane&7 varies fastest within warp (conflict-friendly A loads)
    int rg = (l & 7) | ((w & 3) << 3);    // 0..31
    int cg = (l >> 3) | ((w >> 2) << 2);  // 0..7
    int row0 = rg * 8;
    int col0 = cg * 4;

    unsigned long long acc2[4][4];
#pragma unroll
    for (int i = 0; i < 4; i++)
#pragma unroll
        for (int j = 0; j < 4; j++) acc2[i][j] = 0ull;

    for (int k0 = 0; k0 < K; k0 += GBK) {
        // A tile: 256 rows x 16 k via float4-along-k
#pragma unroll
        for (int i = 0; i < 4; i++) {
            int lin4 = tid + i * 256;
            int r = lin4 >> 2;
            int kk4 = lin4 & 3;
            int gr = bm + r;
            int gk0 = k0 + kk4 * 4;
            float4 a = make_float4(0.f, 0.f, 0.f, 0.f);
            if (gr < N && gk0 + 3 < SA)
                a = *(const float4*)(A + (size_t)gr * SA + gk0);
            As[kk4 * 4 + 0][r] = a.x;
            As[kk4 * 4 + 1][r] = a.y;
            As[kk4 * 4 + 2][r] = a.z;
            As[kk4 * 4 + 3][r] = a.w;
        }
        // B tile: 16 x 32, duplicated
#pragma unroll
        for (int i = 0; i < 2; i++) {
            int lin = tid + i * 256;
            int r = lin >> 5;
            int c = lin & 31;
            int gk = k0 + r, gc = bn + c;
            float bv = (gk < K && gc < M) ? W[(size_t)gk * M + gc] : 0.f;
            Bs2[r][2 * c + 0] = bv;
            Bs2[r][2 * c + 1] = bv;
        }
        __syncthreads();

#pragma unroll
        for (int kk = 0; kk < GBK; kk++) {
            ulonglong2 aL = *(const ulonglong2*)&As[kk][row0];       // rows 0-3
            ulonglong2 aH = *(const ulonglong2*)&As[kk][row0 + 4];   // rows 4-7
            ulonglong2 b01 = *(const ulonglong2*)&Bs2[kk][col0 * 2];     // {b0,b0},{b1,b1}
            ulonglong2 b23 = *(const ulonglong2*)&Bs2[kk][col0 * 2 + 4]; // {b2,b2},{b3,b3}
            ffma2(acc2[0][0], aL.x, b01.x); ffma2(acc2[0][1], aL.x, b01.y);
            ffma2(acc2[0][2], aL.x, b23.x); ffma2(acc2[0][3], aL.x, b23.y);
            ffma2(acc2[1][0], aL.y, b01.x); ffma2(acc2[1][1], aL.y, b01.y);
            ffma2(acc2[1][2], aL.y, b23.x); ffma2(acc2[1][3], aL.y, b23.y);
            ffma2(acc2[2][0], aH.x, b01.x); ffma2(acc2[2][1], aH.x, b01.y);
            ffma2(acc2[2][2], aH.x, b23.x); ffma2(acc2[2][3], aH.x, b23.y);
            ffma2(acc2[3][0], aH.y, b01.x); ffma2(acc2[3][1], aH.y, b01.y);
            ffma2(acc2[3][2], aH.y, b23.x); ffma2(acc2[3][3], aH.y, b23.y);
        }
        __syncthreads();
    }

    // epilogue: each thread owns rows row0..row0+7, cols col0..col0+3
    int gc0 = bn + col0;
#pragma unroll
    for (int rp = 0; rp < 4; rp++) {
        float2 c0 = unpack2(acc2[rp][0]);
        float2 c1 = unpack2(acc2[rp][1]);
        float2 c2 = unpack2(acc2[rp][2]);
        float2 c3 = unpack2(acc2[rp][3]);
        float vlo[4] = {c0.x, c1.x, c2.x, c3.x};   // row row0+2rp
        float vhi[4] = {c0.y, c1.y, c2.y, c3.y};   // row row0+2rp+1
#pragma unroll
        for (int half = 0; half < 2; half++) {
            int gr = bm + row0 + 2 * rp + half;
            if (gr >= N) continue;
            float* vv = half ? vhi : vlo;
            if (fuse_bias_relu) {
#pragma unroll
                for (int j = 0; j < 4; j++)
                    if (gc0 + j < M)                       // FIX: guard bias read
                        vv[j] = fmaxf(vv[j] + bias[gc0 + j], 0.f);
            }
            if (gc0 + 3 < M) {
                *(float4*)(Cout + (size_t)gr * SC + gc0) =
                    make_float4(vv[0], vv[1], vv[2], vv[3]);
            } else {
#pragma unroll
                for (int j = 0; j < 4; j++)
                    if (gc0 + j < M) Cout[(size_t)gr * SC + gc0 + j] = vv[j];
            }
        }
    }
}

// ---------------- final: CSR agg + bias + relu + log_softmax ----------------

__global__ void k_final(const float* __restrict__ t4,       // stride 24
                        const int* __restrict__ row_beg,
                        const int* __restrict__ ideg,
                        const Edge* __restrict__ csr,
                        const float* __restrict__ dinv,
                        const float* __restrict__ b4,
                        float* __restrict__ out_z, float* __restrict__ out_pz, int n) {
    int v = (blockIdx.x * blockDim.x + threadIdx.x) >> 5;
    int lane = threadIdx.x & 31;
    if (v >= n) return;

    float val = -INFINITY;
    if (lane < 21) {
        int beg = row_beg[v];
        int endp = beg + ((ideg[v] + 3) & ~3);
        float acc = 0.f;
        int j = beg;
        for (; j + 8 <= endp; j += 8) {
            int4 e0 = *(const int4*)(csr + j);
            int4 e1 = *(const int4*)(csr + j + 2);
            int4 e2 = *(const int4*)(csr + j + 4);
            int4 e3 = *(const int4*)(csr + j + 6);
            float f0 = t4[(size_t)e0.x * 24 + lane];
            float f1 = t4[(size_t)e0.z * 24 + lane];
            float f2 = t4[(size_t)e1.x * 24 + lane];
            float f3 = t4[(size_t)e1.z * 24 + lane];
            float f4 = t4[(size_t)e2.x * 24 + lane];
            float f5 = t4[(size_t)e2.z * 24 + lane];
            float f6 = t4[(size_t)e3.x * 24 + lane];
            float f7 = t4[(size_t)e3.z * 24 + lane];
            acc = fmaf(__int_as_float(e0.y), f0, acc);
            acc = fmaf(__int_as_float(e0.w), f1, acc);
            acc = fmaf(__int_as_float(e1.y), f2, acc);
            acc = fmaf(__int_as_float(e1.w), f3, acc);
            acc = fmaf(__int_as_float(e2.y), f4, acc);
            acc = fmaf(__int_as_float(e2.w), f5, acc);
            acc = fmaf(__int_as_float(e3.y), f6, acc);
            acc = fmaf(__int_as_float(e3.w), f7, acc);
        }
        if (j < endp) {
            int4 e0 = *(const int4*)(csr + j);
            int4 e1 = *(const int4*)(csr + j + 2);
            float f0 = t4[(size_t)e0.x * 24 + lane];
            float f1 = t4[(size_t)e0.z * 24 + lane];
            float f2 = t4[(size_t)e1.x * 24 + lane];
            float f3 = t4[(size_t)e1.z * 24 + lane];
            acc = fmaf(__int_as_float(e0.y), f0, acc);
            acc = fmaf(__int_as_float(e0.w), f1, acc);
            acc = fmaf(__int_as_float(e1.y), f2, acc);
            acc = fmaf(__int_as_float(e1.w), f3, acc);
        }
        float dv = dinv[v];
        acc = fmaf(dv * dv, t4[(size_t)v * 24 + lane], acc);
        val = fmaxf(acc + b4[lane], 0.f);
    }

    float m = val;
#pragma unroll
    for (int o = 16; o > 0; o >>= 1) m = fmaxf(m, __shfl_xor_sync(0xffffffffu, m, o));
    float ex = (lane < 21) ? __expf(val - m) : 0.f;
    float s = ex;
#pragma unroll
    for (int o = 16; o > 0; o >>= 1) s += __shfl_xor_sync(0xffffffffu, s, o);

    if (lane < 21) {
        out_z[(size_t)v * 21 + lane] = val;
        out_pz[(size_t)v * 21 + lane] = val - m - __logf(s);
    }
}

// ---------------------------------------------------------------------------

static inline int cdiv(long long a, int b) { return (int)((a + b - 1) / b); }

extern "C" void kernel_launch(void* const* d_in, const int* in_sizes, int n_in,
                              void* d_out, int out_size) {
    const float* x  = (const float*)d_in[0];
    const int*   ei = (const int*)d_in[1];
    const float* W1 = (const float*)d_in[2];  const float* b1 = (const float*)d_in[3];
    const float* W2 = (const float*)d_in[4];  const float* b2 = (const float*)d_in[5];
    const float* W3 = (const float*)d_in[6];  const float* b3 = (const float*)d_in[7];
    const float* W4 = (const float*)d_in[8];  const float* b4 = (const float*)d_in[9];

    const int n = in_sizes[0] / 21;
    const int E = in_sizes[1] / 2;

    float *bufA, *bufB, *dinv;
    int *ideg, *row_beg, *cur, *counter;
    Edge* csr;
    cudaGetSymbolAddress((void**)&bufA, g_bufA);
    cudaGetSymbolAddress((void**)&bufB, g_bufB);
    cudaGetSymbolAddress((void**)&dinv, g_dinv);
    cudaGetSymbolAddress((void**)&ideg, g_ideg);
    cudaGetSymbolAddress((void**)&row_beg, g_rowbeg);
    cudaGetSymbolAddress((void**)&cur, g_cur);
    cudaGetSymbolAddress((void**)&counter, g_counter);
    cudaGetSymbolAddress((void**)&csr, g_csr);

    float* out_pz = (float*)d_out;
    float* out_z  = (float*)d_out + (size_t)n * 21;

    const int T = 256;
    const int nb = cdiv(n, SCAN_B);

    // --- CSR build ---
    k_init<<<cdiv(n, T), T>>>(ideg, cur, counter, n);
    k_count_deg<<<cdiv(E, T), T>>>(ei, ideg, E);
    k_offsets<<<nb, SCAN_B>>>(ideg, row_beg, dinv, csr, counter, n);
    k_scatter<<<cdiv(E, T), T>>>(ei, row_beg, cur, dinv, csr, E);

    const int aggGrid = cdiv((long long)n * 32, T);

    // --- layer 1: aggregate x (C=21, stride 21 -> 24), GEMM 21->168 (+bias+relu) ---
    k_agg<21, 1, 21, 24><<<aggGrid, T>>>(x, row_beg, ideg, csr, dinv, nullptr, bufA, n);
    {
        dim3 grid(cdiv(n, GBM), cdiv(168, GBN));
        k_gemm<<<grid, T>>>(bufA, W1, b1, bufB, n, 21, 168, 24, 168, 1);
    }
    // --- layer 2: GEMM 168->84, fused agg+bias+relu (C=84, float4) ---
    {
        dim3 grid(cdiv(n, GBM), cdiv(84, GBN));
        k_gemm<<<grid, T>>>(bufB, W2, nullptr, bufA, n, 168, 84, 168, 84, 0);
    }
    k_agg<84, 4, 84, 84><<<aggGrid, T>>>(bufA, row_beg, ideg, csr, dinv, b2, bufB, n);
    // --- layer 3: GEMM 84->42 (out stride 44), agg (C=42, float2) ---
    {
        dim3 grid(cdiv(n, GBM), cdiv(42, GBN));
        k_gemm<<<grid, T>>>(bufB, W3, nullptr, bufA, n, 84, 42, 84, 44, 0);
    }
    k_agg<42, 2, 44, 44><<<aggGrid, T>>>(bufA, row_beg, ideg, csr, dinv, b3, bufB, n);
    // --- layer 4: GEMM 42->21 (out stride 24), fused final ---
    {
        dim3 grid(cdiv(n, GBM), cdiv(21, GBN));
        k_gemm<<<grid, T>>>(bufB, W4, nullptr, bufA, n, 42, 21, 44, 24, 0);
    }
    k_final<<<aggGrid, T>>>(bufA, row_beg, ideg, csr, dinv, b4, out_z, out_pz, n);
}

// round 6
// speedup vs baseline: 1.3012x; 1.3012x over previous
#include <cuda_runtime.h>
#include <math.h>
#include <stdint.h>

// ---------------------------------------------------------------------------
// graphNet: 4-layer GCN (21->168->84->42->21) + log_softmax.
// Round-6: R3's proven scalar-FFMA 8x4 GEMM (FFMA2 regressed: register-pair
// pressure / f32x2 not full-rate on sm_100a) + R5's 4-launch CSR build.
// ---------------------------------------------------------------------------

#define N_MAX 100000
#define E_MAX 1600000
#define F_MAX 168
#define CSR_MAX (E_MAX + 4 * N_MAX)
#define SCAN_B 1024

struct __align__(8) Edge { int src; float w; };

__device__ float g_bufA[(size_t)N_MAX * F_MAX];
__device__ float g_bufB[(size_t)N_MAX * F_MAX];
__device__ int   g_ideg[N_MAX];
__device__ float g_dinv[N_MAX];
__device__ int   g_rowbeg[N_MAX];
__device__ int   g_cur[N_MAX];
__device__ int   g_counter[1];
__device__ Edge  g_csr[CSR_MAX];

// ---------------- init / degree ----------------

__global__ void k_init(int* __restrict__ ideg, int* __restrict__ cur,
                       int* __restrict__ counter, int n) {
    int i = blockIdx.x * blockDim.x + threadIdx.x;
    if (i < n) { ideg[i] = 0; cur[i] = 0; }
    if (i == 0) counter[0] = 0;
}

__global__ void k_count_deg(const int* __restrict__ ei, int* __restrict__ ideg, int E) {
    int e = blockIdx.x * blockDim.x + threadIdx.x;
    if (e < E) atomicAdd(&ideg[ei[E + e]], 1);
}

// ---------------- fused single-pass offsets ----------------
// Per block: scan padded degrees, grab a global base via atomicAdd (region
// order arbitrary but each node gets a private, correctly sized region).
// Also computes dinv and zero-fills the pad slots of each row.

__global__ void k_offsets(const int* __restrict__ ideg, int* __restrict__ row_beg,
                          float* __restrict__ dinv, Edge* __restrict__ csr,
                          int* __restrict__ counter, int n) {
    __shared__ int s[SCAN_B];
    __shared__ int base_sh;
    int i = blockIdx.x * SCAN_B + threadIdx.x;
    int deg = (i < n) ? ideg[i] : 0;
    int pd = (deg + 3) & ~3;
    s[threadIdx.x] = pd;
    __syncthreads();
#pragma unroll
    for (int off = 1; off < SCAN_B; off <<= 1) {
        int t = (threadIdx.x >= off) ? s[threadIdx.x - off] : 0;
        __syncthreads();
        s[threadIdx.x] += t;
        __syncthreads();
    }
    if (threadIdx.x == SCAN_B - 1) base_sh = atomicAdd(counter, s[SCAN_B - 1]);
    __syncthreads();
    int base = base_sh;
    if (i < n) {
        int beg = base + s[threadIdx.x] - pd;
        row_beg[i] = beg;
        dinv[i] = rsqrtf((float)(deg + 1));
        Edge z; z.src = 0; z.w = 0.f;
        for (int p = deg; p < pd; p++) csr[beg + p] = z;
    }
}

// ---------------- CSR scatter ----------------

__global__ void k_scatter(const int* __restrict__ ei, const int* __restrict__ row_beg,
                          int* __restrict__ cur, const float* __restrict__ dinv,
                          Edge* __restrict__ csr, int E) {
    int e = blockIdx.x * blockDim.x + threadIdx.x;
    if (e < E) {
        int s = ei[e];
        int d = ei[E + e];
        int pos = atomicAdd(&cur[d], 1);
        float2 rec = make_float2(__int_as_float(s), dinv[s] * dinv[d]);
        *reinterpret_cast<float2*>(&csr[row_beg[d] + pos]) = rec;
    }
}

// ---------------- vector row load helper ----------------

template <int VW>
__device__ __forceinline__ void ldrow(float (&f)[VW], const float* __restrict__ p) {
    if (VW == 4) { float4 t = *(const float4*)p; f[0]=t.x; f[1]=t.y; f[2]=t.z; f[3]=t.w; }
    else if (VW == 2) { float2 t = *(const float2*)p; f[0]=t.x; f[1]=t.y; }
    else { f[0] = *p; }
}

// ---------------- fused CSR aggregation ----------------

template <int C, int VW, int SIN, int SOUT>
__global__ void k_agg(const float* __restrict__ h, const int* __restrict__ row_beg,
                      const int* __restrict__ ideg,
                      const Edge* __restrict__ csr, const float* __restrict__ dinv,
                      const float* __restrict__ bias, float* __restrict__ out, int n) {
    constexpr int L = C / VW;
    int v = (blockIdx.x * blockDim.x + threadIdx.x) >> 5;
    int lane = threadIdx.x & 31;
    if (v >= n) return;

    if (lane < L) {
        int beg = row_beg[v];
        int endp = beg + ((ideg[v] + 3) & ~3);
        const int off = lane * VW;
        float acc[VW];
#pragma unroll
        for (int k = 0; k < VW; k++) acc[k] = 0.f;

        int j = beg;
        for (; j + 8 <= endp; j += 8) {
            int4 e0 = *(const int4*)(csr + j);
            int4 e1 = *(const int4*)(csr + j + 2);
            int4 e2 = *(const int4*)(csr + j + 4);
            int4 e3 = *(const int4*)(csr + j + 6);
            float f[8][VW];
            ldrow<VW>(f[0], h + (size_t)e0.x * SIN + off);
            ldrow<VW>(f[1], h + (size_t)e0.z * SIN + off);
            ldrow<VW>(f[2], h + (size_t)e1.x * SIN + off);
            ldrow<VW>(f[3], h + (size_t)e1.z * SIN + off);
            ldrow<VW>(f[4], h + (size_t)e2.x * SIN + off);
            ldrow<VW>(f[5], h + (size_t)e2.z * SIN + off);
            ldrow<VW>(f[6], h + (size_t)e3.x * SIN + off);
            ldrow<VW>(f[7], h + (size_t)e3.z * SIN + off);
            float w[8];
            w[0] = __int_as_float(e0.y); w[1] = __int_as_float(e0.w);
            w[2] = __int_as_float(e1.y); w[3] = __int_as_float(e1.w);
            w[4] = __int_as_float(e2.y); w[5] = __int_as_float(e2.w);
            w[6] = __int_as_float(e3.y); w[7] = __int_as_float(e3.w);
#pragma unroll
            for (int i = 0; i < 8; i++)
#pragma unroll
                for (int k = 0; k < VW; k++) acc[k] = fmaf(w[i], f[i][k], acc[k]);
        }
        if (j < endp) {
            int4 e0 = *(const int4*)(csr + j);
            int4 e1 = *(const int4*)(csr + j + 2);
            float f[4][VW];
            ldrow<VW>(f[0], h + (size_t)e0.x * SIN + off);
            ldrow<VW>(f[1], h + (size_t)e0.z * SIN + off);
            ldrow<VW>(f[2], h + (size_t)e1.x * SIN + off);
            ldrow<VW>(f[3], h + (size_t)e1.z * SIN + off);
            float w[4];
            w[0] = __int_as_float(e0.y); w[1] = __int_as_float(e0.w);
            w[2] = __int_as_float(e1.y); w[3] = __int_as_float(e1.w);
#pragma unroll
            for (int i = 0; i < 4; i++)
#pragma unroll
                for (int k = 0; k < VW; k++) acc[k] = fmaf(w[i], f[i][k], acc[k]);
        }

        float dv = dinv[v];
        float s2 = dv * dv;
        float pvv[VW];
        ldrow<VW>(pvv, h + (size_t)v * SIN + off);
        float* po = out + (size_t)v * SOUT + off;
#pragma unroll
        for (int k = 0; k < VW; k++) {
            float r = fmaf(s2, pvv[k], acc[k]);
            if (bias) r = fmaxf(r + bias[off + k], 0.f);
            po[k] = r;
        }
    } else if (lane * VW < SOUT) {
        float* po = out + (size_t)v * SOUT + lane * VW;
#pragma unroll
        for (int k = 0; k < VW; k++) po[k] = 0.f;
    }
}

// ---------------- GEMM: C[N x M] = A[N x K] @ W[K x M] (+bias, relu) ----------------
// 256x32 block tile, 8x4 microtile, 256 threads (R3's measured-good version).

#define GBM 256
#define GBN 32
#define GBK 16

__global__ void __launch_bounds__(256)
k_gemm(const float* __restrict__ A, const float* __restrict__ W,
       const float* __restrict__ bias, float* __restrict__ Cout,
       int N, int K, int M, int SA, int SC, int fuse_bias_relu) {
    __shared__ float As[GBK][GBM];
    __shared__ float Bs[GBK][GBN];

    int tid = threadIdx.x;
    int bm = blockIdx.x * GBM;
    int bn = blockIdx.y * GBN;
    int ty = tid >> 3;                 // 0..31
    int tx = tid & 7;                  // 0..7
    int row0 = ty * 8;
    int col0 = tx * 4;

    float acc[8][4];
#pragma unroll
    for (int i = 0; i < 8; i++)
#pragma unroll
        for (int j = 0; j < 4; j++) acc[i][j] = 0.f;

    for (int k0 = 0; k0 < K; k0 += GBK) {
        // A tile: 256 rows x 16 k, via float4-along-k (4 per thread)
#pragma unroll
        for (int i = 0; i < 4; i++) {
            int lin4 = tid + i * 256;          // 0..1023
            int r = lin4 >> 2;                 // 0..255
            int kk4 = lin4 & 3;                // which float4 group
            int gr = bm + r;
            int gk0 = k0 + kk4 * 4;
            float4 a = make_float4(0.f, 0.f, 0.f, 0.f);
            if (gr < N && gk0 + 3 < SA)
                a = *(const float4*)(A + (size_t)gr * SA + gk0);
            As[kk4 * 4 + 0][r] = a.x;
            As[kk4 * 4 + 1][r] = a.y;
            As[kk4 * 4 + 2][r] = a.z;
            As[kk4 * 4 + 3][r] = a.w;
        }
        // B tile: 16 x 32 (2 per thread)
#pragma unroll
        for (int i = 0; i < 2; i++) {
            int lin = tid + i * 256;
            int r = lin >> 5;
            int c = lin & 31;
            int gk = k0 + r, gc = bn + c;
            Bs[r][c] = (gk < K && gc < M) ? W[(size_t)gk * M + gc] : 0.f;
        }
        __syncthreads();

#pragma unroll
        for (int kk = 0; kk < GBK; kk++) {
            float4 a0 = *(const float4*)&As[kk][row0];
            float4 a1 = *(const float4*)&As[kk][row0 + 4];
            float4 b  = *(const float4*)&Bs[kk][col0];
            float av[8] = {a0.x, a0.y, a0.z, a0.w, a1.x, a1.y, a1.z, a1.w};
            float bv[4] = {b.x, b.y, b.z, b.w};
#pragma unroll
            for (int i = 0; i < 8; i++)
#pragma unroll
                for (int j = 0; j < 4; j++) acc[i][j] = fmaf(av[i], bv[j], acc[i][j]);
        }
        __syncthreads();
    }

#pragma unroll
    for (int i = 0; i < 8; i++) {
        int gr = bm + row0 + i;
        if (gr < N) {
#pragma unroll
            for (int j = 0; j < 4; j++) {
                int gc = bn + col0 + j;
                if (gc < M) {
                    float v = acc[i][j];
                    if (fuse_bias_relu) v = fmaxf(v + bias[gc], 0.f);
                    Cout[(size_t)gr * SC + gc] = v;
                }
            }
        }
    }
}

// ---------------- final: CSR agg + bias + relu + log_softmax ----------------

__global__ void k_final(const float* __restrict__ t4,       // stride 24
                        const int* __restrict__ row_beg,
                        const int* __restrict__ ideg,
                        const Edge* __restrict__ csr,
                        const float* __restrict__ dinv,
                        const float* __restrict__ b4,
                        float* __restrict__ out_z, float* __restrict__ out_pz, int n) {
    int v = (blockIdx.x * blockDim.x + threadIdx.x) >> 5;
    int lane = threadIdx.x & 31;
    if (v >= n) return;

    float val = -INFINITY;
    if (lane < 21) {
        int beg = row_beg[v];
        int endp = beg + ((ideg[v] + 3) & ~3);
        float acc = 0.f;
        int j = beg;
        for (; j + 8 <= endp; j += 8) {
            int4 e0 = *(const int4*)(csr + j);
            int4 e1 = *(const int4*)(csr + j + 2);
            int4 e2 = *(const int4*)(csr + j + 4);
            int4 e3 = *(const int4*)(csr + j + 6);
            float f0 = t4[(size_t)e0.x * 24 + lane];
            float f1 = t4[(size_t)e0.z * 24 + lane];
            float f2 = t4[(size_t)e1.x * 24 + lane];
            float f3 = t4[(size_t)e1.z * 24 + lane];
            float f4 = t4[(size_t)e2.x * 24 + lane];
            float f5 = t4[(size_t)e2.z * 24 + lane];
            float f6 = t4[(size_t)e3.x * 24 + lane];
            float f7 = t4[(size_t)e3.z * 24 + lane];
            acc = fmaf(__int_as_float(e0.y), f0, acc);
            acc = fmaf(__int_as_float(e0.w), f1, acc);
            acc = fmaf(__int_as_float(e1.y), f2, acc);
            acc = fmaf(__int_as_float(e1.w), f3, acc);
            acc = fmaf(__int_as_float(e2.y), f4, acc);
            acc = fmaf(__int_as_float(e2.w), f5, acc);
            acc = fmaf(__int_as_float(e3.y), f6, acc);
            acc = fmaf(__int_as_float(e3.w), f7, acc);
        }
        if (j < endp) {
            int4 e0 = *(const int4*)(csr + j);
            int4 e1 = *(const int4*)(csr + j + 2);
            float f0 = t4[(size_t)e0.x * 24 + lane];
            float f1 = t4[(size_t)e0.z * 24 + lane];
            float f2 = t4[(size_t)e1.x * 24 + lane];
            float f3 = t4[(size_t)e1.z * 24 + lane];
            acc = fmaf(__int_as_float(e0.y), f0, acc);
            acc = fmaf(__int_as_float(e0.w), f1, acc);
            acc = fmaf(__int_as_float(e1.y), f2, acc);
            acc = fmaf(__int_as_float(e1.w), f3, acc);
        }
        float dv = dinv[v];
        acc = fmaf(dv * dv, t4[(size_t)v * 24 + lane], acc);
        val = fmaxf(acc + b4[lane], 0.f);
    }

    float m = val;
#pragma unroll
    for (int o = 16; o > 0; o >>= 1) m = fmaxf(m, __shfl_xor_sync(0xffffffffu, m, o));
    float ex = (lane < 21) ? __expf(val - m) : 0.f;
    float s = ex;
#pragma unroll
    for (int o = 16; o > 0; o >>= 1) s += __shfl_xor_sync(0xffffffffu, s, o);

    if (lane < 21) {
        out_z[(size_t)v * 21 + lane] = val;
        out_pz[(size_t)v * 21 + lane] = val - m - __logf(s);
    }
}

// ---------------------------------------------------------------------------

static inline int cdiv(long long a, int b) { return (int)((a + b - 1) / b); }

extern "C" void kernel_launch(void* const* d_in, const int* in_sizes, int n_in,
                              void* d_out, int out_size) {
    const float* x  = (const float*)d_in[0];
    const int*   ei = (const int*)d_in[1];
    const float* W1 = (const float*)d_in[2];  const float* b1 = (const float*)d_in[3];
    const float* W2 = (const float*)d_in[4];  const float* b2 = (const float*)d_in[5];
    const float* W3 = (const float*)d_in[6];  const float* b3 = (const float*)d_in[7];
    const float* W4 = (const float*)d_in[8];  const float* b4 = (const float*)d_in[9];

    const int n = in_sizes[0] / 21;
    const int E = in_sizes[1] / 2;

    float *bufA, *bufB, *dinv;
    int *ideg, *row_beg, *cur, *counter;
    Edge* csr;
    cudaGetSymbolAddress((void**)&bufA, g_bufA);
    cudaGetSymbolAddress((void**)&bufB, g_bufB);
    cudaGetSymbolAddress((void**)&dinv, g_dinv);
    cudaGetSymbolAddress((void**)&ideg, g_ideg);
    cudaGetSymbolAddress((void**)&row_beg, g_rowbeg);
    cudaGetSymbolAddress((void**)&cur, g_cur);
    cudaGetSymbolAddress((void**)&counter, g_counter);
    cudaGetSymbolAddress((void**)&csr, g_csr);

    float* out_pz = (float*)d_out;
    float* out_z  = (float*)d_out + (size_t)n * 21;

    const int T = 256;
    const int nb = cdiv(n, SCAN_B);

    // --- CSR build (4 launches) ---
    k_init<<<cdiv(n, T), T>>>(ideg, cur, counter, n);
    k_count_deg<<<cdiv(E, T), T>>>(ei, ideg, E);
    k_offsets<<<nb, SCAN_B>>>(ideg, row_beg, dinv, csr, counter, n);
    k_scatter<<<cdiv(E, T), T>>>(ei, row_beg, cur, dinv, csr, E);

    const int aggGrid = cdiv((long long)n * 32, T);

    // --- layer 1: aggregate x (C=21, stride 21 -> 24), GEMM 21->168 (+bias+relu) ---
    k_agg<21, 1, 21, 24><<<aggGrid, T>>>(x, row_beg, ideg, csr, dinv, nullptr, bufA, n);
    {
        dim3 grid(cdiv(n, GBM), cdiv(168, GBN));
        k_gemm<<<grid, T>>>(bufA, W1, b1, bufB, n, 21, 168, 24, 168, 1);
    }
    // --- layer 2: GEMM 168->84, fused agg+bias+relu (C=84, float4) ---
    {
        dim3 grid(cdiv(n, GBM), cdiv(84, GBN));
        k_gemm<<<grid, T>>>(bufB, W2, nullptr, bufA, n, 168, 84, 168, 84, 0);
    }
    k_agg<84, 4, 84, 84><<<aggGrid, T>>>(bufA, row_beg, ideg, csr, dinv, b2, bufB, n);
    // --- layer 3: GEMM 84->42 (out stride 44), agg (C=42, float2) ---
    {
        dim3 grid(cdiv(n, GBM), cdiv(42, GBN));
        k_gemm<<<grid, T>>>(bufB, W3, nullptr, bufA, n, 84, 42, 84, 44, 0);
    }
    k_agg<42, 2, 44, 44><<<aggGrid, T>>>(bufA, row_beg, ideg, csr, dinv, b3, bufB, n);
    // --- layer 4: GEMM 42->21 (out stride 24), fused final ---
    {
        dim3 grid(cdiv(n, GBM), cdiv(21, GBN));
        k_gemm<<<grid, T>>>(bufB, W4, nullptr, bufA, n, 42, 21, 44, 24, 0);
    }
    k_final<<<aggGrid, T>>>(bufA, row_beg, ideg, csr, dinv, b4, out_z, out_pz, n);
}